// round 1
// baseline (speedup 1.0000x reference)
#include <cuda_runtime.h>
#include <cuda_bf16.h>
#include <cstdint>

// Problem sizes
#define BB   128
#define TT   256
#define CC   384
#define HH   6
#define HSZ  64
#define MTOT (BB*TT)          // 32768

// Scratch ( __device__ globals are the sanctioned scratch mechanism )
__device__ float g_q[BB*HH*TT*HSZ];    // [B][H][T][64]
__device__ float g_k[BB*HH*TT*HSZ];
__device__ float g_v[BB*HH*TT*HSZ];
__device__ float g_att[BB*TT*HH*HSZ];  // [B][T][384]  (head-concat, proj-ready)

__device__ __forceinline__ unsigned f2tf32(float x) {
    unsigned u;
    asm("cvt.rna.tf32.f32 %0, %1;" : "=r"(u) : "f"(x));
    return u;
}

__device__ __forceinline__ void mma8(float& c0, float& c1, float& c2, float& c3,
                                     unsigned a0, unsigned a1, unsigned a2, unsigned a3,
                                     unsigned b0, unsigned b1) {
    asm volatile(
        "mma.sync.aligned.m16n8k8.row.col.f32.tf32.tf32.f32 "
        "{%0,%1,%2,%3}, {%4,%5,%6,%7}, {%8,%9}, {%0,%1,%2,%3};\n"
        : "+f"(c0), "+f"(c1), "+f"(c2), "+f"(c3)
        : "r"(a0), "r"(a1), "r"(a2), "r"(a3), "r"(b0), "r"(b1));
}

// ---------------------------------------------------------------------------
// Kernel 1: fused QKV projection GEMM
//   M = 32768 (b*T+t), N = 1152 (which*384 + h*64 + d), K = 384
//   A = x row-major;  B(k=c, n) = W_which[h][c][d]
// CTA tile 128x128, 8 warps (2x4) of 64x32, BK=32.
// ---------------------------------------------------------------------------
__global__ void __launch_bounds__(256) qkv_gemm_kernel(
    const float* __restrict__ x,
    const float* __restrict__ Wq,
    const float* __restrict__ Wk,
    const float* __restrict__ Wv)
{
    __shared__ unsigned As[128][33];   // [m][k]
    __shared__ unsigned Bs[128][33];   // [n][k]

    const int tid  = threadIdx.x;
    const int wid  = tid >> 5;
    const int lane = tid & 31;
    const int g    = lane >> 2;
    const int qd   = lane & 3;

    const int mb = blockIdx.y * 128;
    const int nb = blockIdx.x * 128;
    const int wm = (wid >> 2) * 64;
    const int wn = (wid & 3) * 32;

    float acc[4][4][4];
    #pragma unroll
    for (int i = 0; i < 4; i++)
        #pragma unroll
        for (int j = 0; j < 4; j++)
            #pragma unroll
            for (int r = 0; r < 4; r++) acc[i][j][r] = 0.f;

    for (int kt = 0; kt < 12; ++kt) {
        const int k0 = kt * 32;
        // Load A tile: 128x32 via float4
        #pragma unroll
        for (int it = 0; it < 4; ++it) {
            int idx = tid + it * 256;
            int m   = idx >> 3;
            int k4  = (idx & 7) * 4;
            float4 v = *(const float4*)(x + (size_t)(mb + m) * CC + k0 + k4);
            As[m][k4 + 0] = f2tf32(v.x);
            As[m][k4 + 1] = f2tf32(v.y);
            As[m][k4 + 2] = f2tf32(v.z);
            As[m][k4 + 3] = f2tf32(v.w);
        }
        // Load B tile: 32x128 scalar (gather across Wq/Wk/Wv head layout)
        #pragma unroll
        for (int it = 0; it < 16; ++it) {
            int idx = tid + it * 256;
            int kk  = idx >> 7;          // 0..31
            int n   = idx & 127;
            int ng  = nb + n;
            int which = ng / 384;
            int rem   = ng - which * 384;
            int hh    = rem >> 6;
            int dd    = rem & 63;
            const float* W = (which == 0) ? Wq : ((which == 1) ? Wk : Wv);
            float v = W[hh * (CC * HSZ) + (k0 + kk) * HSZ + dd];
            Bs[n][kk] = f2tf32(v);
        }
        __syncthreads();

        #pragma unroll
        for (int ks = 0; ks < 4; ++ks) {
            unsigned af[4][4];
            unsigned bf[4][2];
            const int c = ks * 8 + qd;
            #pragma unroll
            for (int im = 0; im < 4; im++) {
                int r = wm + 16 * im + g;
                af[im][0] = As[r][c];
                af[im][1] = As[r + 8][c];
                af[im][2] = As[r][c + 4];
                af[im][3] = As[r + 8][c + 4];
            }
            #pragma unroll
            for (int jn = 0; jn < 4; jn++) {
                int n = wn + 8 * jn + g;
                bf[jn][0] = Bs[n][c];
                bf[jn][1] = Bs[n][c + 4];
            }
            #pragma unroll
            for (int im = 0; im < 4; im++)
                #pragma unroll
                for (int jn = 0; jn < 4; jn++)
                    mma8(acc[im][jn][0], acc[im][jn][1], acc[im][jn][2], acc[im][jn][3],
                         af[im][0], af[im][1], af[im][2], af[im][3],
                         bf[jn][0], bf[jn][1]);
        }
        __syncthreads();
    }

    // Epilogue: scatter into q/k/v [B][H][T][64]
    #pragma unroll
    for (int im = 0; im < 4; im++) {
        #pragma unroll
        for (int jn = 0; jn < 4; jn++) {
            int mg = mb + wm + 16 * im + g;
            int ng = nb + wn + 8 * jn + 2 * qd;
            int which = ng / 384;
            int rem   = ng - which * 384;
            int hh    = rem >> 6;
            int dd    = rem & 63;
            float* buf = (which == 0) ? g_q : ((which == 1) ? g_k : g_v);
            int b0i = mg >> 8, t0i = mg & 255;
            float2 v01 = make_float2(acc[im][jn][0], acc[im][jn][1]);
            *(float2*)(buf + ((b0i * HH + hh) * TT + t0i) * HSZ + dd) = v01;
            int mg2 = mg + 8;
            int b1i = mg2 >> 8, t1i = mg2 & 255;
            float2 v23 = make_float2(acc[im][jn][2], acc[im][jn][3]);
            *(float2*)(buf + ((b1i * HH + hh) * TT + t1i) * HSZ + dd) = v23;
        }
    }
}

// ---------------------------------------------------------------------------
// Kernel 2: causal flash attention, one CTA per (b,h).
// Q,K,V (256x64 each, tf32 bits) resident in SMEM (stride 68 -> conflict-free).
// 8 warps x 32 query rows; key blocks of 64 with causal block skipping.
// ---------------------------------------------------------------------------
#define SM_STRIDE 68
#define SM_ONE (TT * SM_STRIDE)     // 17408 words per tensor

__global__ void __launch_bounds__(256, 1) attn_kernel()
{
    extern __shared__ unsigned smem[];
    unsigned* Qs = smem;
    unsigned* Ks = smem + SM_ONE;
    unsigned* Vs = smem + 2 * SM_ONE;

    const int bh = blockIdx.x;
    const int b  = bh / HH;
    const int h  = bh - b * HH;

    const int tid  = threadIdx.x;
    const int w    = tid >> 5;
    const int lane = tid & 31;
    const int g    = lane >> 2;
    const int qd   = lane & 3;

    const float* qsrc = g_q + (size_t)bh * (TT * HSZ);
    const float* ksrc = g_k + (size_t)bh * (TT * HSZ);
    const float* vsrc = g_v + (size_t)bh * (TT * HSZ);

    // Stage Q (pre-scaled), K, V into SMEM as tf32 bits
    #pragma unroll
    for (int j = 0; j < 16; ++j) {
        int lin = tid + 256 * j;
        int r   = lin >> 4;
        int c4  = (lin & 15) * 4;
        float4 vq = *(const float4*)(qsrc + r * HSZ + c4);
        Qs[r * SM_STRIDE + c4 + 0] = f2tf32(vq.x * 0.125f);
        Qs[r * SM_STRIDE + c4 + 1] = f2tf32(vq.y * 0.125f);
        Qs[r * SM_STRIDE + c4 + 2] = f2tf32(vq.z * 0.125f);
        Qs[r * SM_STRIDE + c4 + 3] = f2tf32(vq.w * 0.125f);
        float4 vk = *(const float4*)(ksrc + r * HSZ + c4);
        Ks[r * SM_STRIDE + c4 + 0] = f2tf32(vk.x);
        Ks[r * SM_STRIDE + c4 + 1] = f2tf32(vk.y);
        Ks[r * SM_STRIDE + c4 + 2] = f2tf32(vk.z);
        Ks[r * SM_STRIDE + c4 + 3] = f2tf32(vk.w);
        float4 vv = *(const float4*)(vsrc + r * HSZ + c4);
        Vs[r * SM_STRIDE + c4 + 0] = f2tf32(vv.x);
        Vs[r * SM_STRIDE + c4 + 1] = f2tf32(vv.y);
        Vs[r * SM_STRIDE + c4 + 2] = f2tf32(vv.z);
        Vs[r * SM_STRIDE + c4 + 3] = f2tf32(vv.w);
    }
    __syncthreads();

    float o[2][8][4];
    #pragma unroll
    for (int i = 0; i < 2; i++)
        #pragma unroll
        for (int j = 0; j < 8; j++)
            #pragma unroll
            for (int r = 0; r < 4; r++) o[i][j][r] = 0.f;

    float row_max[2][2] = {{-1e30f, -1e30f}, {-1e30f, -1e30f}};
    float row_sum[2][2] = {{0.f, 0.f}, {0.f, 0.f}};

    const int jbmax = (32 * w + 31) / 64;   // causal block skip

    for (int jb = 0; jb <= jbmax; ++jb) {
        // ---- S = Q K^T (accum fp32) ----
        float s[2][8][4];
        #pragma unroll
        for (int i = 0; i < 2; i++)
            #pragma unroll
            for (int j = 0; j < 8; j++)
                #pragma unroll
                for (int r = 0; r < 4; r++) s[i][j][r] = 0.f;

        #pragma unroll
        for (int ks = 0; ks < 8; ++ks) {
            const int c = ks * 8 + qd;
            unsigned af[2][4];
            #pragma unroll
            for (int im = 0; im < 2; im++) {
                int r = 32 * w + 16 * im + g;
                af[im][0] = Qs[r * SM_STRIDE + c];
                af[im][1] = Qs[(r + 8) * SM_STRIDE + c];
                af[im][2] = Qs[r * SM_STRIDE + c + 4];
                af[im][3] = Qs[(r + 8) * SM_STRIDE + c + 4];
            }
            #pragma unroll
            for (int jn = 0; jn < 8; jn++) {
                int srow = jb * 64 + 8 * jn + g;
                unsigned b0 = Ks[srow * SM_STRIDE + c];
                unsigned b1 = Ks[srow * SM_STRIDE + c + 4];
                #pragma unroll
                for (int im = 0; im < 2; im++)
                    mma8(s[im][jn][0], s[im][jn][1], s[im][jn][2], s[im][jn][3],
                         af[im][0], af[im][1], af[im][2], af[im][3], b0, b1);
            }
        }

        // ---- causal mask + online softmax ----
        #pragma unroll
        for (int im = 0; im < 2; im++) {
            #pragma unroll
            for (int hf = 0; hf < 2; hf++) {
                int trow = 32 * w + 16 * im + 8 * hf + g;
                float rmax = -1e30f;
                #pragma unroll
                for (int jn = 0; jn < 8; jn++) {
                    #pragma unroll
                    for (int e = 0; e < 2; e++) {
                        int col = jb * 64 + 8 * jn + 2 * qd + e;
                        float v = s[im][jn][2 * hf + e];
                        if (col > trow) v = -1e30f;
                        s[im][jn][2 * hf + e] = v;
                        rmax = fmaxf(rmax, v);
                    }
                }
                rmax = fmaxf(rmax, __shfl_xor_sync(0xffffffffu, rmax, 1));
                rmax = fmaxf(rmax, __shfl_xor_sync(0xffffffffu, rmax, 2));
                float mnew = fmaxf(row_max[im][hf], rmax);
                float corr = __expf(row_max[im][hf] - mnew);
                row_max[im][hf] = mnew;
                float psum = 0.f;
                #pragma unroll
                for (int jn = 0; jn < 8; jn++) {
                    #pragma unroll
                    for (int e = 0; e < 2; e++) {
                        float p = __expf(s[im][jn][2 * hf + e] - mnew);
                        s[im][jn][2 * hf + e] = p;
                        psum += p;
                    }
                }
                psum += __shfl_xor_sync(0xffffffffu, psum, 1);
                psum += __shfl_xor_sync(0xffffffffu, psum, 2);
                row_sum[im][hf] = row_sum[im][hf] * corr + psum;
                #pragma unroll
                for (int jn = 0; jn < 8; jn++) {
                    o[im][jn][2 * hf + 0] *= corr;
                    o[im][jn][2 * hf + 1] *= corr;
                }
            }
        }

        // ---- O += P V  (accum-layout -> A-layout via shuffles) ----
        const int src1 = 4 * g + (qd >> 1);
        const int src2 = src1 + 2;
        const bool oddq = (qd & 1);
        #pragma unroll
        for (int ks = 0; ks < 8; ++ks) {
            unsigned pa[2][4];
            #pragma unroll
            for (int im = 0; im < 2; im++) {
                float v00 = __shfl_sync(0xffffffffu, s[im][ks][0], src1);
                float v01 = __shfl_sync(0xffffffffu, s[im][ks][1], src1);
                float v20 = __shfl_sync(0xffffffffu, s[im][ks][2], src1);
                float v21 = __shfl_sync(0xffffffffu, s[im][ks][3], src1);
                float v40 = __shfl_sync(0xffffffffu, s[im][ks][0], src2);
                float v41 = __shfl_sync(0xffffffffu, s[im][ks][1], src2);
                float v60 = __shfl_sync(0xffffffffu, s[im][ks][2], src2);
                float v61 = __shfl_sync(0xffffffffu, s[im][ks][3], src2);
                pa[im][0] = f2tf32(oddq ? v01 : v00);
                pa[im][1] = f2tf32(oddq ? v21 : v20);
                pa[im][2] = f2tf32(oddq ? v41 : v40);
                pa[im][3] = f2tf32(oddq ? v61 : v60);
            }
            int krow = jb * 64 + 8 * ks;
            #pragma unroll
            for (int jn = 0; jn < 8; jn++) {
                unsigned vb0 = Vs[(krow + qd) * SM_STRIDE + 8 * jn + g];
                unsigned vb1 = Vs[(krow + qd + 4) * SM_STRIDE + 8 * jn + g];
                #pragma unroll
                for (int im = 0; im < 2; im++)
                    mma8(o[im][jn][0], o[im][jn][1], o[im][jn][2], o[im][jn][3],
                         pa[im][0], pa[im][1], pa[im][2], pa[im][3], vb0, vb1);
            }
        }
    }

    // ---- normalize + store to g_att [B][T][384] ----
    #pragma unroll
    for (int im = 0; im < 2; im++) {
        float inv0 = 1.0f / row_sum[im][0];
        float inv1 = 1.0f / row_sum[im][1];
        #pragma unroll
        for (int jn = 0; jn < 8; jn++) {
            int trow = 32 * w + 16 * im + g;
            int dd   = 8 * jn + 2 * qd;
            float2 v01 = make_float2(o[im][jn][0] * inv0, o[im][jn][1] * inv0);
            *(float2*)(g_att + (size_t)(b * TT + trow) * CC + h * HSZ + dd) = v01;
            float2 v23 = make_float2(o[im][jn][2] * inv1, o[im][jn][3] * inv1);
            *(float2*)(g_att + (size_t)(b * TT + trow + 8) * CC + h * HSZ + dd) = v23;
        }
    }
}

// ---------------------------------------------------------------------------
// Kernel 3: output projection  out = att @ Wp^T + bp
//   M=32768, N=384, K=384.  B(k=j, n=i) = Wp[i][j] -> plain row-major load.
// ---------------------------------------------------------------------------
__global__ void __launch_bounds__(256) proj_gemm_kernel(
    const float* __restrict__ Wp,
    const float* __restrict__ bp,
    float* __restrict__ out)
{
    __shared__ unsigned As[128][33];   // [m][k]
    __shared__ unsigned Bs[128][33];   // [n][k]

    const int tid  = threadIdx.x;
    const int wid  = tid >> 5;
    const int lane = tid & 31;
    const int g    = lane >> 2;
    const int qd   = lane & 3;

    const int mb = blockIdx.y * 128;
    const int nb = blockIdx.x * 128;
    const int wm = (wid >> 2) * 64;
    const int wn = (wid & 3) * 32;

    float acc[4][4][4];
    #pragma unroll
    for (int i = 0; i < 4; i++)
        #pragma unroll
        for (int j = 0; j < 4; j++)
            #pragma unroll
            for (int r = 0; r < 4; r++) acc[i][j][r] = 0.f;

    for (int kt = 0; kt < 12; ++kt) {
        const int k0 = kt * 32;
        #pragma unroll
        for (int it = 0; it < 4; ++it) {
            int idx = tid + it * 256;
            int m   = idx >> 3;
            int k4  = (idx & 7) * 4;
            float4 v = *(const float4*)(g_att + (size_t)(mb + m) * CC + k0 + k4);
            As[m][k4 + 0] = f2tf32(v.x);
            As[m][k4 + 1] = f2tf32(v.y);
            As[m][k4 + 2] = f2tf32(v.z);
            As[m][k4 + 3] = f2tf32(v.w);
        }
        #pragma unroll
        for (int it = 0; it < 4; ++it) {
            int idx = tid + it * 256;
            int n   = idx >> 3;
            int k4  = (idx & 7) * 4;
            float4 v = *(const float4*)(Wp + (size_t)(nb + n) * CC + k0 + k4);
            Bs[n][k4 + 0] = f2tf32(v.x);
            Bs[n][k4 + 1] = f2tf32(v.y);
            Bs[n][k4 + 2] = f2tf32(v.z);
            Bs[n][k4 + 3] = f2tf32(v.w);
        }
        __syncthreads();

        #pragma unroll
        for (int ks = 0; ks < 4; ++ks) {
            unsigned af[4][4];
            unsigned bf[4][2];
            const int c = ks * 8 + qd;
            #pragma unroll
            for (int im = 0; im < 4; im++) {
                int r = wm + 16 * im + g;
                af[im][0] = As[r][c];
                af[im][1] = As[r + 8][c];
                af[im][2] = As[r][c + 4];
                af[im][3] = As[r + 8][c + 4];
            }
            #pragma unroll
            for (int jn = 0; jn < 4; jn++) {
                int n = wn + 8 * jn + g;
                bf[jn][0] = Bs[n][c];
                bf[jn][1] = Bs[n][c + 4];
            }
            #pragma unroll
            for (int im = 0; im < 4; im++)
                #pragma unroll
                for (int jn = 0; jn < 4; jn++)
                    mma8(acc[im][jn][0], acc[im][jn][1], acc[im][jn][2], acc[im][jn][3],
                         af[im][0], af[im][1], af[im][2], af[im][3],
                         bf[jn][0], bf[jn][1]);
        }
        __syncthreads();
    }

    #pragma unroll
    for (int im = 0; im < 4; im++) {
        #pragma unroll
        for (int jn = 0; jn < 4; jn++) {
            int mg = mb + wm + 16 * im + g;
            int ng = nb + wn + 8 * jn + 2 * qd;
            float b0v = bp[ng], b1v = bp[ng + 1];
            float2 v01 = make_float2(acc[im][jn][0] + b0v, acc[im][jn][1] + b1v);
            *(float2*)(out + (size_t)mg * CC + ng) = v01;
            float2 v23 = make_float2(acc[im][jn][2] + b0v, acc[im][jn][3] + b1v);
            *(float2*)(out + (size_t)(mg + 8) * CC + ng) = v23;
        }
    }
}

// ---------------------------------------------------------------------------
extern "C" void kernel_launch(void* const* d_in, const int* in_sizes, int n_in,
                              void* d_out, int out_size)
{
    const float* x  = (const float*)d_in[0];
    const float* Wq = (const float*)d_in[1];
    const float* Wk = (const float*)d_in[2];
    const float* Wv = (const float*)d_in[3];
    const float* Wp = (const float*)d_in[4];
    const float* bp = (const float*)d_in[5];
    float* out = (float*)d_out;

    const int attn_smem = 3 * SM_ONE * 4;   // 208896 bytes
    cudaFuncSetAttribute(attn_kernel, cudaFuncAttributeMaxDynamicSharedMemorySize, attn_smem);

    qkv_gemm_kernel<<<dim3(9, 256), 256>>>(x, Wq, Wk, Wv);
    attn_kernel<<<BB * HH, 256, attn_smem>>>();
    proj_gemm_kernel<<<dim3(3, 256), 256>>>(Wp, bp, out);
}

// round 2
// speedup vs baseline: 1.9287x; 1.9287x over previous
#include <cuda_runtime.h>
#include <cuda_bf16.h>
#include <cstdint>

// Problem sizes
#define BB   128
#define TT   256
#define CC   384
#define HH   6
#define HSZ  64
#define MTOT (BB*TT)          // 32768
#define NQKV 1152

// Scratch (tf32 bit patterns stored as unsigned)
__device__ unsigned g_xt[MTOT*CC];        // x converted to tf32
__device__ unsigned g_wqkv[NQKV*CC];      // packed B[n][k], Wq pre-scaled by 0.125
__device__ unsigned g_wp[CC*CC];          // Wp[n][k] tf32
__device__ unsigned g_q[BB*HH*TT*HSZ];    // [B][H][T][64] tf32 (pre-scaled)
__device__ unsigned g_k[BB*HH*TT*HSZ];
__device__ unsigned g_v[BB*HH*TT*HSZ];
__device__ unsigned g_att[MTOT*CC];       // [B][T][384] tf32

__device__ __forceinline__ unsigned f2tf32(float x) {
    unsigned u;
    asm("cvt.rna.tf32.f32 %0, %1;" : "=r"(u) : "f"(x));
    return u;
}

__device__ __forceinline__ void cp_async16(unsigned* smem_dst, const unsigned* gsrc) {
    unsigned s = (unsigned)__cvta_generic_to_shared(smem_dst);
    asm volatile("cp.async.cg.shared.global [%0], [%1], 16;\n" :: "r"(s), "l"(gsrc));
}
#define CP_COMMIT() asm volatile("cp.async.commit_group;\n" ::: "memory")
#define CP_WAIT(N)  asm volatile("cp.async.wait_group %0;\n" :: "n"(N) : "memory")

__device__ __forceinline__ void mma8(float& c0, float& c1, float& c2, float& c3,
                                     unsigned a0, unsigned a1, unsigned a2, unsigned a3,
                                     unsigned b0, unsigned b1) {
    asm volatile(
        "mma.sync.aligned.m16n8k8.row.col.f32.tf32.tf32.f32 "
        "{%0,%1,%2,%3}, {%4,%5,%6,%7}, {%8,%9}, {%0,%1,%2,%3};\n"
        : "+f"(c0), "+f"(c1), "+f"(c2), "+f"(c3)
        : "r"(a0), "r"(a1), "r"(a2), "r"(a3), "r"(b0), "r"(b1));
}

// ---------------------------------------------------------------------------
// Prep: convert x to tf32
// ---------------------------------------------------------------------------
__global__ void __launch_bounds__(256) conv_x_kernel(const float* __restrict__ x) {
    int i = (blockIdx.x * 256 + threadIdx.x) * 4;
    float4 v = *(const float4*)(x + i);
    uint4 o;
    o.x = f2tf32(v.x); o.y = f2tf32(v.y); o.z = f2tf32(v.z); o.w = f2tf32(v.w);
    *(uint4*)(g_xt + i) = o;
}

// Prep: pack Wq/Wk/Wv as B[n][k] (n = which*384 + h*64 + d, k = c), Wq scaled 0.125
//        and Wp as B[n][k] (row-major already)
__global__ void __launch_bounds__(256) pack_w_kernel(
    const float* __restrict__ Wq, const float* __restrict__ Wk,
    const float* __restrict__ Wv, const float* __restrict__ Wp) {
    int i = blockIdx.x * 256 + threadIdx.x;
    if (i < NQKV * CC) {
        int n = i / CC, k = i - (i / CC) * CC;
        int which = n / CC;
        int rem = n - which * CC;
        int h = rem >> 6, d = rem & 63;
        const float* W = (which == 0) ? Wq : ((which == 1) ? Wk : Wv);
        float v = W[h * (CC * HSZ) + k * HSZ + d];
        if (which == 0) v *= 0.125f;
        g_wqkv[i] = f2tf32(v);
    }
    if (i < CC * CC) {
        g_wp[i] = f2tf32(Wp[i]);
    }
}

// ---------------------------------------------------------------------------
// Kernel 1: fused QKV projection GEMM, cp.async 2-stage pipeline
//   M = 32768, N = 1152, K = 384. CTA 128x128, 8 warps 64x32, BK=32.
// SMEM per stage: A 128x36 words + B 128x36 words. Stage stride 4608 words.
// ---------------------------------------------------------------------------
#define GSTR 36
#define STGW (128*GSTR)   // 4608 words

__device__ __forceinline__ void gemm_prefetch(unsigned* smA, unsigned* smB,
                                              const unsigned* gA, const unsigned* gB,
                                              int tid) {
    #pragma unroll
    for (int it = 0; it < 4; ++it) {
        int idx = tid + it * 256;
        int row = idx >> 3, ch = idx & 7;
        cp_async16(smA + row * GSTR + ch * 4, gA + (size_t)row * CC + ch * 4);
        cp_async16(smB + row * GSTR + ch * 4, gB + (size_t)row * CC + ch * 4);
    }
}

__global__ void __launch_bounds__(256, 2) qkv_gemm_kernel()
{
    extern __shared__ unsigned sm[];
    const int tid  = threadIdx.x;
    const int wid  = tid >> 5;
    const int lane = tid & 31;
    const int g    = lane >> 2;
    const int qd   = lane & 3;

    const int mb = blockIdx.y * 128;
    const int nb = blockIdx.x * 128;
    const int wm = (wid >> 2) * 64;
    const int wn = (wid & 3) * 32;

    const unsigned* gA = g_xt + (size_t)mb * CC;
    const unsigned* gB = g_wqkv + (size_t)nb * CC;

    float acc[4][4][4];
    #pragma unroll
    for (int i = 0; i < 4; i++)
        #pragma unroll
        for (int j = 0; j < 4; j++)
            #pragma unroll
            for (int r = 0; r < 4; r++) acc[i][j][r] = 0.f;

    gemm_prefetch(sm, sm + 2 * STGW, gA, gB, tid);
    CP_COMMIT();

    for (int kt = 0; kt < 12; ++kt) {
        if (kt < 11) {
            int s = (kt + 1) & 1;
            gemm_prefetch(sm + s * STGW, sm + 2 * STGW + s * STGW,
                          gA + (kt + 1) * 32, gB + (kt + 1) * 32, tid);
            CP_COMMIT();
            CP_WAIT(1);
        } else {
            CP_WAIT(0);
        }
        __syncthreads();

        const unsigned* A = sm + (kt & 1) * STGW;
        const unsigned* B = sm + 2 * STGW + (kt & 1) * STGW;

        #pragma unroll
        for (int ks = 0; ks < 4; ++ks) {
            unsigned af[4][4];
            unsigned bf[4][2];
            const int c = ks * 8 + qd;
            #pragma unroll
            for (int im = 0; im < 4; im++) {
                int r = wm + 16 * im + g;
                af[im][0] = A[r * GSTR + c];
                af[im][1] = A[(r + 8) * GSTR + c];
                af[im][2] = A[r * GSTR + c + 4];
                af[im][3] = A[(r + 8) * GSTR + c + 4];
            }
            #pragma unroll
            for (int jn = 0; jn < 4; jn++) {
                int n = wn + 8 * jn + g;
                bf[jn][0] = B[n * GSTR + c];
                bf[jn][1] = B[n * GSTR + c + 4];
            }
            #pragma unroll
            for (int im = 0; im < 4; im++)
                #pragma unroll
                for (int jn = 0; jn < 4; jn++)
                    mma8(acc[im][jn][0], acc[im][jn][1], acc[im][jn][2], acc[im][jn][3],
                         af[im][0], af[im][1], af[im][2], af[im][3],
                         bf[jn][0], bf[jn][1]);
        }
        __syncthreads();
    }

    // Epilogue: scatter tf32 bits into q/k/v [B][H][T][64]
    #pragma unroll
    for (int im = 0; im < 4; im++) {
        #pragma unroll
        for (int jn = 0; jn < 4; jn++) {
            int mg = mb + wm + 16 * im + g;
            int ng = nb + wn + 8 * jn + 2 * qd;
            int which = ng / CC;
            int rem   = ng - which * CC;
            int hh    = rem >> 6;
            int dd    = rem & 63;
            unsigned* buf = (which == 0) ? g_q : ((which == 1) ? g_k : g_v);
            int b0i = mg >> 8, t0i = mg & 255;
            uint2 v01; v01.x = f2tf32(acc[im][jn][0]); v01.y = f2tf32(acc[im][jn][1]);
            *(uint2*)(buf + ((b0i * HH + hh) * TT + t0i) * HSZ + dd) = v01;
            int mg2 = mg + 8;
            int b1i = mg2 >> 8, t1i = mg2 & 255;
            uint2 v23; v23.x = f2tf32(acc[im][jn][2]); v23.y = f2tf32(acc[im][jn][3]);
            *(uint2*)(buf + ((b1i * HH + hh) * TT + t1i) * HSZ + dd) = v23;
        }
    }
}

// ---------------------------------------------------------------------------
// Kernel 2: causal flash attention, one CTA per (b,h), load-balanced slabs.
// Warp w owns 16-row slabs at 16w and 240-16w  -> every warp = 2.5 block-units.
// ---------------------------------------------------------------------------
#define SM_STRIDE 68
#define SM_ONE (TT * SM_STRIDE)     // 17408 words per tensor

__global__ void __launch_bounds__(256, 1) attn_kernel()
{
    extern __shared__ unsigned smem[];
    unsigned* Qs = smem;
    unsigned* Ks = smem + SM_ONE;
    unsigned* Vs = smem + 2 * SM_ONE;

    const int bh = blockIdx.x;
    const int b  = bh / HH;
    const int h  = bh - b * HH;

    const int tid  = threadIdx.x;
    const int w    = tid >> 5;
    const int lane = tid & 31;
    const int g    = lane >> 2;
    const int qd   = lane & 3;

    const unsigned* qsrc = g_q + (size_t)bh * (TT * HSZ);
    const unsigned* ksrc = g_k + (size_t)bh * (TT * HSZ);
    const unsigned* vsrc = g_v + (size_t)bh * (TT * HSZ);

    // Stage Q,K,V (already tf32, Q pre-scaled) via cp.async
    #pragma unroll
    for (int j = 0; j < 16; ++j) {
        int lin = tid + 256 * j;
        int r   = lin >> 4;
        int ch  = lin & 15;
        cp_async16(Qs + r * SM_STRIDE + ch * 4, qsrc + r * HSZ + ch * 4);
        cp_async16(Ks + r * SM_STRIDE + ch * 4, ksrc + r * HSZ + ch * 4);
        cp_async16(Vs + r * SM_STRIDE + ch * 4, vsrc + r * HSZ + ch * 4);
    }
    CP_COMMIT();
    CP_WAIT(0);
    __syncthreads();

    const int rbs[2] = { 16 * w, 240 - 16 * w };
    const int jbmax0 = (rbs[0] + 15) >> 6;
    const int jbmax1 = (rbs[1] + 15) >> 6;

    float o[2][8][4];
    #pragma unroll
    for (int i = 0; i < 2; i++)
        #pragma unroll
        for (int j = 0; j < 8; j++)
            #pragma unroll
            for (int r = 0; r < 4; r++) o[i][j][r] = 0.f;

    float row_max[2][2] = {{-1e30f, -1e30f}, {-1e30f, -1e30f}};
    float row_sum[2][2] = {{0.f, 0.f}, {0.f, 0.f}};

    for (int jb = 0; jb <= jbmax1; ++jb) {
        const bool act0 = (jb <= jbmax0);

        // ---- S = Q K^T ----
        float s[2][8][4];
        #pragma unroll
        for (int i = 0; i < 2; i++)
            #pragma unroll
            for (int j = 0; j < 8; j++)
                #pragma unroll
                for (int r = 0; r < 4; r++) s[i][j][r] = 0.f;

        #pragma unroll
        for (int ks = 0; ks < 8; ++ks) {
            const int c = ks * 8 + qd;
            unsigned af[2][4];
            {
                int r = rbs[1] + g;
                af[1][0] = Qs[r * SM_STRIDE + c];
                af[1][1] = Qs[(r + 8) * SM_STRIDE + c];
                af[1][2] = Qs[r * SM_STRIDE + c + 4];
                af[1][3] = Qs[(r + 8) * SM_STRIDE + c + 4];
            }
            if (act0) {
                int r = rbs[0] + g;
                af[0][0] = Qs[r * SM_STRIDE + c];
                af[0][1] = Qs[(r + 8) * SM_STRIDE + c];
                af[0][2] = Qs[r * SM_STRIDE + c + 4];
                af[0][3] = Qs[(r + 8) * SM_STRIDE + c + 4];
            }
            #pragma unroll
            for (int jn = 0; jn < 8; jn++) {
                int srow = jb * 64 + 8 * jn + g;
                unsigned b0 = Ks[srow * SM_STRIDE + c];
                unsigned b1 = Ks[srow * SM_STRIDE + c + 4];
                mma8(s[1][jn][0], s[1][jn][1], s[1][jn][2], s[1][jn][3],
                     af[1][0], af[1][1], af[1][2], af[1][3], b0, b1);
                if (act0)
                    mma8(s[0][jn][0], s[0][jn][1], s[0][jn][2], s[0][jn][3],
                         af[0][0], af[0][1], af[0][2], af[0][3], b0, b1);
            }
        }

        // ---- causal mask + online softmax ----
        #pragma unroll
        for (int im = 0; im < 2; im++) {
            if (im == 0 && !act0) continue;
            #pragma unroll
            for (int hf = 0; hf < 2; hf++) {
                int trow = rbs[im] + 8 * hf + g;
                float rmax = -1e30f;
                #pragma unroll
                for (int jn = 0; jn < 8; jn++) {
                    #pragma unroll
                    for (int e = 0; e < 2; e++) {
                        int col = jb * 64 + 8 * jn + 2 * qd + e;
                        float v = s[im][jn][2 * hf + e];
                        if (col > trow) v = -1e30f;
                        s[im][jn][2 * hf + e] = v;
                        rmax = fmaxf(rmax, v);
                    }
                }
                rmax = fmaxf(rmax, __shfl_xor_sync(0xffffffffu, rmax, 1));
                rmax = fmaxf(rmax, __shfl_xor_sync(0xffffffffu, rmax, 2));
                float mnew = fmaxf(row_max[im][hf], rmax);
                float corr = __expf(row_max[im][hf] - mnew);
                row_max[im][hf] = mnew;
                float psum = 0.f;
                #pragma unroll
                for (int jn = 0; jn < 8; jn++) {
                    #pragma unroll
                    for (int e = 0; e < 2; e++) {
                        float p = __expf(s[im][jn][2 * hf + e] - mnew);
                        s[im][jn][2 * hf + e] = p;
                        psum += p;
                    }
                }
                psum += __shfl_xor_sync(0xffffffffu, psum, 1);
                psum += __shfl_xor_sync(0xffffffffu, psum, 2);
                row_sum[im][hf] = row_sum[im][hf] * corr + psum;
                #pragma unroll
                for (int jn = 0; jn < 8; jn++) {
                    o[im][jn][2 * hf + 0] *= corr;
                    o[im][jn][2 * hf + 1] *= corr;
                }
            }
        }

        // ---- O += P V ----
        const int src1 = 4 * g + (qd >> 1);
        const int src2 = src1 + 2;
        const bool oddq = (qd & 1);
        #pragma unroll
        for (int ks = 0; ks < 8; ++ks) {
            unsigned pa[2][4];
            #pragma unroll
            for (int im = 0; im < 2; im++) {
                if (im == 0 && !act0) continue;
                float v00 = __shfl_sync(0xffffffffu, s[im][ks][0], src1);
                float v01 = __shfl_sync(0xffffffffu, s[im][ks][1], src1);
                float v20 = __shfl_sync(0xffffffffu, s[im][ks][2], src1);
                float v21 = __shfl_sync(0xffffffffu, s[im][ks][3], src1);
                float v40 = __shfl_sync(0xffffffffu, s[im][ks][0], src2);
                float v41 = __shfl_sync(0xffffffffu, s[im][ks][1], src2);
                float v60 = __shfl_sync(0xffffffffu, s[im][ks][2], src2);
                float v61 = __shfl_sync(0xffffffffu, s[im][ks][3], src2);
                pa[im][0] = f2tf32(oddq ? v01 : v00);
                pa[im][1] = f2tf32(oddq ? v21 : v20);
                pa[im][2] = f2tf32(oddq ? v41 : v40);
                pa[im][3] = f2tf32(oddq ? v61 : v60);
            }
            int krow = jb * 64 + 8 * ks;
            #pragma unroll
            for (int jn = 0; jn < 8; jn++) {
                unsigned vb0 = Vs[(krow + qd) * SM_STRIDE + 8 * jn + g];
                unsigned vb1 = Vs[(krow + qd + 4) * SM_STRIDE + 8 * jn + g];
                mma8(o[1][jn][0], o[1][jn][1], o[1][jn][2], o[1][jn][3],
                     pa[1][0], pa[1][1], pa[1][2], pa[1][3], vb0, vb1);
                if (act0)
                    mma8(o[0][jn][0], o[0][jn][1], o[0][jn][2], o[0][jn][3],
                         pa[0][0], pa[0][1], pa[0][2], pa[0][3], vb0, vb1);
            }
        }
    }

    // ---- normalize + store tf32 bits to g_att [B][T][384] ----
    #pragma unroll
    for (int im = 0; im < 2; im++) {
        float inv0 = 1.0f / row_sum[im][0];
        float inv1 = 1.0f / row_sum[im][1];
        #pragma unroll
        for (int jn = 0; jn < 8; jn++) {
            int trow = rbs[im] + g;
            int dd   = 8 * jn + 2 * qd;
            uint2 v01; v01.x = f2tf32(o[im][jn][0] * inv0); v01.y = f2tf32(o[im][jn][1] * inv0);
            *(uint2*)(g_att + (size_t)(b * TT + trow) * CC + h * HSZ + dd) = v01;
            uint2 v23; v23.x = f2tf32(o[im][jn][2] * inv1); v23.y = f2tf32(o[im][jn][3] * inv1);
            *(uint2*)(g_att + (size_t)(b * TT + trow + 8) * CC + h * HSZ + dd) = v23;
        }
    }
}

// ---------------------------------------------------------------------------
// Kernel 3: output projection  out = att @ Wp^T + bp  (M=32768, N=384, K=384)
// Same cp.async 2-stage structure.
// ---------------------------------------------------------------------------
__global__ void __launch_bounds__(256, 2) proj_gemm_kernel(
    const float* __restrict__ bp,
    float* __restrict__ out)
{
    extern __shared__ unsigned sm[];
    const int tid  = threadIdx.x;
    const int wid  = tid >> 5;
    const int lane = tid & 31;
    const int g    = lane >> 2;
    const int qd   = lane & 3;

    const int mb = blockIdx.y * 128;
    const int nb = blockIdx.x * 128;
    const int wm = (wid >> 2) * 64;
    const int wn = (wid & 3) * 32;

    const unsigned* gA = g_att + (size_t)mb * CC;
    const unsigned* gB = g_wp + (size_t)nb * CC;

    float acc[4][4][4];
    #pragma unroll
    for (int i = 0; i < 4; i++)
        #pragma unroll
        for (int j = 0; j < 4; j++)
            #pragma unroll
            for (int r = 0; r < 4; r++) acc[i][j][r] = 0.f;

    gemm_prefetch(sm, sm + 2 * STGW, gA, gB, tid);
    CP_COMMIT();

    for (int kt = 0; kt < 12; ++kt) {
        if (kt < 11) {
            int s = (kt + 1) & 1;
            gemm_prefetch(sm + s * STGW, sm + 2 * STGW + s * STGW,
                          gA + (kt + 1) * 32, gB + (kt + 1) * 32, tid);
            CP_COMMIT();
            CP_WAIT(1);
        } else {
            CP_WAIT(0);
        }
        __syncthreads();

        const unsigned* A = sm + (kt & 1) * STGW;
        const unsigned* B = sm + 2 * STGW + (kt & 1) * STGW;

        #pragma unroll
        for (int ks = 0; ks < 4; ++ks) {
            unsigned af[4][4];
            unsigned bf[4][2];
            const int c = ks * 8 + qd;
            #pragma unroll
            for (int im = 0; im < 4; im++) {
                int r = wm + 16 * im + g;
                af[im][0] = A[r * GSTR + c];
                af[im][1] = A[(r + 8) * GSTR + c];
                af[im][2] = A[r * GSTR + c + 4];
                af[im][3] = A[(r + 8) * GSTR + c + 4];
            }
            #pragma unroll
            for (int jn = 0; jn < 4; jn++) {
                int n = wn + 8 * jn + g;
                bf[jn][0] = B[n * GSTR + c];
                bf[jn][1] = B[n * GSTR + c + 4];
            }
            #pragma unroll
            for (int im = 0; im < 4; im++)
                #pragma unroll
                for (int jn = 0; jn < 4; jn++)
                    mma8(acc[im][jn][0], acc[im][jn][1], acc[im][jn][2], acc[im][jn][3],
                         af[im][0], af[im][1], af[im][2], af[im][3],
                         bf[jn][0], bf[jn][1]);
        }
        __syncthreads();
    }

    #pragma unroll
    for (int im = 0; im < 4; im++) {
        #pragma unroll
        for (int jn = 0; jn < 4; jn++) {
            int mg = mb + wm + 16 * im + g;
            int ng = nb + wn + 8 * jn + 2 * qd;
            float b0v = bp[ng], b1v = bp[ng + 1];
            float2 v01 = make_float2(acc[im][jn][0] + b0v, acc[im][jn][1] + b1v);
            *(float2*)(out + (size_t)mg * CC + ng) = v01;
            float2 v23 = make_float2(acc[im][jn][2] + b0v, acc[im][jn][3] + b1v);
            *(float2*)(out + (size_t)(mg + 8) * CC + ng) = v23;
        }
    }
}

// ---------------------------------------------------------------------------
extern "C" void kernel_launch(void* const* d_in, const int* in_sizes, int n_in,
                              void* d_out, int out_size)
{
    const float* x  = (const float*)d_in[0];
    const float* Wq = (const float*)d_in[1];
    const float* Wk = (const float*)d_in[2];
    const float* Wv = (const float*)d_in[3];
    const float* Wp = (const float*)d_in[4];
    const float* bp = (const float*)d_in[5];
    float* out = (float*)d_out;

    static bool attr_set = false;
    const int gemm_smem = 4 * STGW * 4;     // 73728 B
    const int attn_smem = 3 * SM_ONE * 4;   // 208896 B
    if (!attr_set) {
        cudaFuncSetAttribute(qkv_gemm_kernel,  cudaFuncAttributeMaxDynamicSharedMemorySize, gemm_smem);
        cudaFuncSetAttribute(proj_gemm_kernel, cudaFuncAttributeMaxDynamicSharedMemorySize, gemm_smem);
        cudaFuncSetAttribute(attn_kernel,      cudaFuncAttributeMaxDynamicSharedMemorySize, attn_smem);
        attr_set = true;
    }

    conv_x_kernel<<<MTOT * CC / (256 * 4), 256>>>(x);
    pack_w_kernel<<<(NQKV * CC + 255) / 256, 256>>>(Wq, Wk, Wv, Wp);
    qkv_gemm_kernel<<<dim3(9, 256), 256, gemm_smem>>>();
    attn_kernel<<<BB * HH, 256, attn_smem>>>();
    proj_gemm_kernel<<<dim3(3, 256), 256, gemm_smem>>>(bp, out);
}

// round 3
// speedup vs baseline: 2.1399x; 1.1095x over previous
#include <cuda_runtime.h>
#include <cuda_bf16.h>
#include <cstdint>

// Problem sizes
#define BB   128
#define TT   256
#define CC   384
#define HH   6
#define HSZ  64
#define MTOT (BB*TT)          // 32768
#define NQKV 1152

// Scratch (tf32 bit patterns stored as unsigned)
__device__ unsigned g_xt[MTOT*CC];        // x converted to tf32
__device__ unsigned g_wqkv[NQKV*CC];      // packed B[n][k], Wq pre-scaled by 0.125
__device__ unsigned g_wp[CC*CC];          // Wp[n][k] tf32
__device__ unsigned g_q[BB*HH*TT*HSZ];    // [B][H][T][64] tf32 (pre-scaled)
__device__ unsigned g_k[BB*HH*TT*HSZ];
__device__ unsigned g_v[BB*HH*TT*HSZ];
__device__ unsigned g_att[MTOT*CC];       // [B][T][384] tf32

__device__ __forceinline__ unsigned f2tf32(float x) {
    unsigned u;
    asm("cvt.rna.tf32.f32 %0, %1;" : "=r"(u) : "f"(x));
    return u;
}

__device__ __forceinline__ void cp_async16(unsigned* smem_dst, const unsigned* gsrc) {
    unsigned s = (unsigned)__cvta_generic_to_shared(smem_dst);
    asm volatile("cp.async.cg.shared.global [%0], [%1], 16;\n" :: "r"(s), "l"(gsrc));
}
#define CP_COMMIT() asm volatile("cp.async.commit_group;\n" ::: "memory")
#define CP_WAIT(N)  asm volatile("cp.async.wait_group %0;\n" :: "n"(N) : "memory")

__device__ __forceinline__ void mma8(float& c0, float& c1, float& c2, float& c3,
                                     unsigned a0, unsigned a1, unsigned a2, unsigned a3,
                                     unsigned b0, unsigned b1) {
    asm volatile(
        "mma.sync.aligned.m16n8k8.row.col.f32.tf32.tf32.f32 "
        "{%0,%1,%2,%3}, {%4,%5,%6,%7}, {%8,%9}, {%0,%1,%2,%3};\n"
        : "+f"(c0), "+f"(c1), "+f"(c2), "+f"(c3)
        : "r"(a0), "r"(a1), "r"(a2), "r"(a3), "r"(b0), "r"(b1));
}

// bit-reverse-3 XOR swizzle (16B-aligned: multiples of 4 words)
__device__ __forceinline__ int swz(int r) {
    return ((r & 1) << 4) | ((r & 2) << 2) | (r & 4);
}

// ---------------------------------------------------------------------------
// Prep kernels
// ---------------------------------------------------------------------------
__global__ void __launch_bounds__(256) conv_x_kernel(const float* __restrict__ x) {
    int i = (blockIdx.x * 256 + threadIdx.x) * 4;
    float4 v = *(const float4*)(x + i);
    uint4 o;
    o.x = f2tf32(v.x); o.y = f2tf32(v.y); o.z = f2tf32(v.z); o.w = f2tf32(v.w);
    *(uint4*)(g_xt + i) = o;
}

__global__ void __launch_bounds__(256) pack_w_kernel(
    const float* __restrict__ Wq, const float* __restrict__ Wk,
    const float* __restrict__ Wv, const float* __restrict__ Wp) {
    int i = blockIdx.x * 256 + threadIdx.x;
    if (i < NQKV * CC) {
        int n = i / CC, k = i - (i / CC) * CC;
        int which = n / CC;
        int rem = n - which * CC;
        int h = rem >> 6, d = rem & 63;
        const float* W = (which == 0) ? Wq : ((which == 1) ? Wk : Wv);
        float v = W[h * (CC * HSZ) + k * HSZ + d];
        if (which == 0) v *= 0.125f;
        g_wqkv[i] = f2tf32(v);
    }
    if (i < CC * CC) {
        g_wp[i] = f2tf32(Wp[i]);
    }
}

// ---------------------------------------------------------------------------
// GEMM kernels (unchanged from R2): cp.async 2-stage, CTA 128x128, 8 warps.
// ---------------------------------------------------------------------------
#define GSTR 36
#define STGW (128*GSTR)   // 4608 words

__device__ __forceinline__ void gemm_prefetch(unsigned* smA, unsigned* smB,
                                              const unsigned* gA, const unsigned* gB,
                                              int tid) {
    #pragma unroll
    for (int it = 0; it < 4; ++it) {
        int idx = tid + it * 256;
        int row = idx >> 3, ch = idx & 7;
        cp_async16(smA + row * GSTR + ch * 4, gA + (size_t)row * CC + ch * 4);
        cp_async16(smB + row * GSTR + ch * 4, gB + (size_t)row * CC + ch * 4);
    }
}

__global__ void __launch_bounds__(256, 2) qkv_gemm_kernel()
{
    extern __shared__ unsigned sm[];
    const int tid  = threadIdx.x;
    const int wid  = tid >> 5;
    const int lane = tid & 31;
    const int g    = lane >> 2;
    const int qd   = lane & 3;

    const int mb = blockIdx.y * 128;
    const int nb = blockIdx.x * 128;
    const int wm = (wid >> 2) * 64;
    const int wn = (wid & 3) * 32;

    const unsigned* gA = g_xt + (size_t)mb * CC;
    const unsigned* gB = g_wqkv + (size_t)nb * CC;

    float acc[4][4][4];
    #pragma unroll
    for (int i = 0; i < 4; i++)
        #pragma unroll
        for (int j = 0; j < 4; j++)
            #pragma unroll
            for (int r = 0; r < 4; r++) acc[i][j][r] = 0.f;

    gemm_prefetch(sm, sm + 2 * STGW, gA, gB, tid);
    CP_COMMIT();

    for (int kt = 0; kt < 12; ++kt) {
        if (kt < 11) {
            int s = (kt + 1) & 1;
            gemm_prefetch(sm + s * STGW, sm + 2 * STGW + s * STGW,
                          gA + (kt + 1) * 32, gB + (kt + 1) * 32, tid);
            CP_COMMIT();
            CP_WAIT(1);
        } else {
            CP_WAIT(0);
        }
        __syncthreads();

        const unsigned* A = sm + (kt & 1) * STGW;
        const unsigned* B = sm + 2 * STGW + (kt & 1) * STGW;

        #pragma unroll
        for (int ks = 0; ks < 4; ++ks) {
            unsigned af[4][4];
            unsigned bf[4][2];
            const int c = ks * 8 + qd;
            #pragma unroll
            for (int im = 0; im < 4; im++) {
                int r = wm + 16 * im + g;
                af[im][0] = A[r * GSTR + c];
                af[im][1] = A[(r + 8) * GSTR + c];
                af[im][2] = A[r * GSTR + c + 4];
                af[im][3] = A[(r + 8) * GSTR + c + 4];
            }
            #pragma unroll
            for (int jn = 0; jn < 4; jn++) {
                int n = wn + 8 * jn + g;
                bf[jn][0] = B[n * GSTR + c];
                bf[jn][1] = B[n * GSTR + c + 4];
            }
            #pragma unroll
            for (int im = 0; im < 4; im++)
                #pragma unroll
                for (int jn = 0; jn < 4; jn++)
                    mma8(acc[im][jn][0], acc[im][jn][1], acc[im][jn][2], acc[im][jn][3],
                         af[im][0], af[im][1], af[im][2], af[im][3],
                         bf[jn][0], bf[jn][1]);
        }
        __syncthreads();
    }

    #pragma unroll
    for (int im = 0; im < 4; im++) {
        #pragma unroll
        for (int jn = 0; jn < 4; jn++) {
            int mg = mb + wm + 16 * im + g;
            int ng = nb + wn + 8 * jn + 2 * qd;
            int which = ng / CC;
            int rem   = ng - which * CC;
            int hh    = rem >> 6;
            int dd    = rem & 63;
            unsigned* buf = (which == 0) ? g_q : ((which == 1) ? g_k : g_v);
            int b0i = mg >> 8, t0i = mg & 255;
            uint2 v01; v01.x = f2tf32(acc[im][jn][0]); v01.y = f2tf32(acc[im][jn][1]);
            *(uint2*)(buf + ((b0i * HH + hh) * TT + t0i) * HSZ + dd) = v01;
            int mg2 = mg + 8;
            int b1i = mg2 >> 8, t1i = mg2 & 255;
            uint2 v23; v23.x = f2tf32(acc[im][jn][2]); v23.y = f2tf32(acc[im][jn][3]);
            *(uint2*)(buf + ((b1i * HH + hh) * TT + t1i) * HSZ + dd) = v23;
        }
    }
}

// ---------------------------------------------------------------------------
// Kernel 2 (REWORKED): causal flash attention.
// CTA = (bh, half): 128 query rows, 8 warps x 16 rows. 2 CTAs/SM target.
// SMEM: Q region 32KB resident + 2 KV stages of 32KB (K 16KB + V 16KB) = 96KB.
// KV streamed in 64-row chunks via cp.async; XOR swizzle, compact stride 64.
// ---------------------------------------------------------------------------
#define AQ_WORDS 8192                 // Q region: 128 rows x 64 words
#define AST_WORDS 8192                // one stage: K 4096 + V 4096 words
#define ATTN_SMEM ((AQ_WORDS + 2*AST_WORDS) * 4)   // 98304 bytes

__global__ void __launch_bounds__(256, 2) attn_kernel()
{
    extern __shared__ unsigned sm[];
    unsigned* Qs = sm;                       // [128][64] swizzled

    const int bh   = blockIdx.x;
    const int half = 1 - blockIdx.y;         // heavy half (rows 128-255) first
    const int b    = bh / HH;
    const int h    = bh - b * HH;

    const int tid  = threadIdx.x;
    const int w    = tid >> 5;
    const int lane = tid & 31;
    const int g    = lane >> 2;
    const int qd   = lane & 3;

    const unsigned* qsrc = g_q + (size_t)bh * (TT * HSZ) + half * 128 * HSZ;
    const unsigned* ksrc = g_k + (size_t)bh * (TT * HSZ);
    const unsigned* vsrc = g_v + (size_t)bh * (TT * HSZ);

    // Stage Q (128 rows) + KV chunk 0, one group
    #pragma unroll
    for (int i = 0; i < 8; i++) {
        int lin = tid + 256 * i;             // 0..2047
        int r = lin >> 4, ch = lin & 15;
        cp_async16(Qs + r * 64 + ((ch * 4) ^ swz(r & 7)), qsrc + r * HSZ + ch * 4);
    }
    {
        unsigned* st = sm + AQ_WORDS;        // stage 0
        #pragma unroll
        for (int i = 0; i < 4; i++) {
            int lin = tid + 256 * i;         // 0..1023
            int r = lin >> 4, ch = lin & 15;
            int phys = r * 64 + ((ch * 4) ^ swz(r & 7));
            cp_async16(st + phys,        ksrc + r * HSZ + ch * 4);
            cp_async16(st + 4096 + phys, vsrc + r * HSZ + ch * 4);
        }
    }
    CP_COMMIT();

    const int jbmax_w = (half * 128 + 16 * w + 15) >> 6;
    const int jbmax_c = half ? 3 : 1;

    float o[8][4];
    #pragma unroll
    for (int j = 0; j < 8; j++)
        #pragma unroll
        for (int r = 0; r < 4; r++) o[j][r] = 0.f;
    float row_max[2] = {-1e30f, -1e30f};
    float row_sum[2] = {0.f, 0.f};

    const int r0 = 16 * w + g;               // local Q row
    const int sg = swz(g);

    for (int jb = 0; jb <= jbmax_c; ++jb) {
        CP_WAIT(0);
        __syncthreads();
        if (jb < jbmax_c) {
            unsigned* st = sm + AQ_WORDS + ((jb + 1) & 1) * AST_WORDS;
            const unsigned* kg = ksrc + (jb + 1) * 64 * HSZ;
            const unsigned* vg = vsrc + (jb + 1) * 64 * HSZ;
            #pragma unroll
            for (int i = 0; i < 4; i++) {
                int lin = tid + 256 * i;
                int r = lin >> 4, ch = lin & 15;
                int phys = r * 64 + ((ch * 4) ^ swz(r & 7));
                cp_async16(st + phys,        kg + r * HSZ + ch * 4);
                cp_async16(st + 4096 + phys, vg + r * HSZ + ch * 4);
            }
            CP_COMMIT();
        }

        if (jb <= jbmax_w) {
            const unsigned* K = sm + AQ_WORDS + (jb & 1) * AST_WORDS;
            const unsigned* V = K + 4096;

            // ---- S = Q K^T ----
            float s[8][4];
            #pragma unroll
            for (int j = 0; j < 8; j++)
                #pragma unroll
                for (int r = 0; r < 4; r++) s[j][r] = 0.f;

            #pragma unroll
            for (int ks = 0; ks < 8; ++ks) {
                const int cs = (8 * ks + qd) ^ sg;
                unsigned a0 = Qs[r0 * 64 + cs];
                unsigned a1 = Qs[(r0 + 8) * 64 + cs];
                unsigned a2 = Qs[r0 * 64 + (cs ^ 4)];
                unsigned a3 = Qs[(r0 + 8) * 64 + (cs ^ 4)];
                #pragma unroll
                for (int jn = 0; jn < 8; jn++) {
                    unsigned b0 = K[(8 * jn + g) * 64 + cs];
                    unsigned b1 = K[(8 * jn + g) * 64 + (cs ^ 4)];
                    mma8(s[jn][0], s[jn][1], s[jn][2], s[jn][3],
                         a0, a1, a2, a3, b0, b1);
                }
            }

            // ---- causal mask + online softmax ----
            #pragma unroll
            for (int hf = 0; hf < 2; hf++) {
                int trow = half * 128 + 16 * w + 8 * hf + g;
                float rmax = -1e30f;
                #pragma unroll
                for (int jn = 0; jn < 8; jn++) {
                    #pragma unroll
                    for (int e = 0; e < 2; e++) {
                        int col = jb * 64 + 8 * jn + 2 * qd + e;
                        float v = s[jn][2 * hf + e];
                        if (col > trow) v = -1e30f;
                        s[jn][2 * hf + e] = v;
                        rmax = fmaxf(rmax, v);
                    }
                }
                rmax = fmaxf(rmax, __shfl_xor_sync(0xffffffffu, rmax, 1));
                rmax = fmaxf(rmax, __shfl_xor_sync(0xffffffffu, rmax, 2));
                float mnew = fmaxf(row_max[hf], rmax);
                float corr = __expf(row_max[hf] - mnew);
                row_max[hf] = mnew;
                float psum = 0.f;
                #pragma unroll
                for (int jn = 0; jn < 8; jn++) {
                    #pragma unroll
                    for (int e = 0; e < 2; e++) {
                        float p = __expf(s[jn][2 * hf + e] - mnew);
                        s[jn][2 * hf + e] = p;
                        psum += p;
                    }
                }
                psum += __shfl_xor_sync(0xffffffffu, psum, 1);
                psum += __shfl_xor_sync(0xffffffffu, psum, 2);
                row_sum[hf] = row_sum[hf] * corr + psum;
                #pragma unroll
                for (int jn = 0; jn < 8; jn++) {
                    o[jn][2 * hf + 0] *= corr;
                    o[jn][2 * hf + 1] *= corr;
                }
            }

            // ---- O += P V ----
            const int src1 = 4 * g + (qd >> 1);
            const int src2 = src1 + 2;
            const bool oddq = (qd & 1);
            const int svq0 = swz(qd), svq1 = swz(qd + 4);
            #pragma unroll
            for (int ks = 0; ks < 8; ++ks) {
                float v00 = __shfl_sync(0xffffffffu, s[ks][0], src1);
                float v01 = __shfl_sync(0xffffffffu, s[ks][1], src1);
                float v20 = __shfl_sync(0xffffffffu, s[ks][2], src1);
                float v21 = __shfl_sync(0xffffffffu, s[ks][3], src1);
                float v40 = __shfl_sync(0xffffffffu, s[ks][0], src2);
                float v41 = __shfl_sync(0xffffffffu, s[ks][1], src2);
                float v60 = __shfl_sync(0xffffffffu, s[ks][2], src2);
                float v61 = __shfl_sync(0xffffffffu, s[ks][3], src2);
                unsigned pa0 = f2tf32(oddq ? v01 : v00);
                unsigned pa1 = f2tf32(oddq ? v21 : v20);
                unsigned pa2 = f2tf32(oddq ? v41 : v40);
                unsigned pa3 = f2tf32(oddq ? v61 : v60);
                const int vr0 = (8 * ks + qd) * 64;
                const int vr1 = (8 * ks + qd + 4) * 64;
                #pragma unroll
                for (int jn = 0; jn < 8; jn++) {
                    unsigned vb0 = V[vr0 + ((8 * jn + g) ^ svq0)];
                    unsigned vb1 = V[vr1 + ((8 * jn + g) ^ svq1)];
                    mma8(o[jn][0], o[jn][1], o[jn][2], o[jn][3],
                         pa0, pa1, pa2, pa3, vb0, vb1);
                }
            }
        }
    }

    // ---- normalize + store tf32 bits to g_att [B][T][384] ----
    float inv0 = 1.0f / row_sum[0];
    float inv1 = 1.0f / row_sum[1];
    int trow = half * 128 + 16 * w + g;
    #pragma unroll
    for (int jn = 0; jn < 8; jn++) {
        int dd = 8 * jn + 2 * qd;
        uint2 v01; v01.x = f2tf32(o[jn][0] * inv0); v01.y = f2tf32(o[jn][1] * inv0);
        *(uint2*)(g_att + (size_t)(b * TT + trow) * CC + h * HSZ + dd) = v01;
        uint2 v23; v23.x = f2tf32(o[jn][2] * inv1); v23.y = f2tf32(o[jn][3] * inv1);
        *(uint2*)(g_att + (size_t)(b * TT + trow + 8) * CC + h * HSZ + dd) = v23;
    }
}

// ---------------------------------------------------------------------------
// Kernel 3: output projection (unchanged from R2)
// ---------------------------------------------------------------------------
__global__ void __launch_bounds__(256, 2) proj_gemm_kernel(
    const float* __restrict__ bp,
    float* __restrict__ out)
{
    extern __shared__ unsigned sm[];
    const int tid  = threadIdx.x;
    const int wid  = tid >> 5;
    const int lane = tid & 31;
    const int g    = lane >> 2;
    const int qd   = lane & 3;

    const int mb = blockIdx.y * 128;
    const int nb = blockIdx.x * 128;
    const int wm = (wid >> 2) * 64;
    const int wn = (wid & 3) * 32;

    const unsigned* gA = g_att + (size_t)mb * CC;
    const unsigned* gB = g_wp + (size_t)nb * CC;

    float acc[4][4][4];
    #pragma unroll
    for (int i = 0; i < 4; i++)
        #pragma unroll
        for (int j = 0; j < 4; j++)
            #pragma unroll
            for (int r = 0; r < 4; r++) acc[i][j][r] = 0.f;

    gemm_prefetch(sm, sm + 2 * STGW, gA, gB, tid);
    CP_COMMIT();

    for (int kt = 0; kt < 12; ++kt) {
        if (kt < 11) {
            int s = (kt + 1) & 1;
            gemm_prefetch(sm + s * STGW, sm + 2 * STGW + s * STGW,
                          gA + (kt + 1) * 32, gB + (kt + 1) * 32, tid);
            CP_COMMIT();
            CP_WAIT(1);
        } else {
            CP_WAIT(0);
        }
        __syncthreads();

        const unsigned* A = sm + (kt & 1) * STGW;
        const unsigned* B = sm + 2 * STGW + (kt & 1) * STGW;

        #pragma unroll
        for (int ks = 0; ks < 4; ++ks) {
            unsigned af[4][4];
            unsigned bf[4][2];
            const int c = ks * 8 + qd;
            #pragma unroll
            for (int im = 0; im < 4; im++) {
                int r = wm + 16 * im + g;
                af[im][0] = A[r * GSTR + c];
                af[im][1] = A[(r + 8) * GSTR + c];
                af[im][2] = A[r * GSTR + c + 4];
                af[im][3] = A[(r + 8) * GSTR + c + 4];
            }
            #pragma unroll
            for (int jn = 0; jn < 4; jn++) {
                int n = wn + 8 * jn + g;
                bf[jn][0] = B[n * GSTR + c];
                bf[jn][1] = B[n * GSTR + c + 4];
            }
            #pragma unroll
            for (int im = 0; im < 4; im++)
                #pragma unroll
                for (int jn = 0; jn < 4; jn++)
                    mma8(acc[im][jn][0], acc[im][jn][1], acc[im][jn][2], acc[im][jn][3],
                         af[im][0], af[im][1], af[im][2], af[im][3],
                         bf[jn][0], bf[jn][1]);
        }
        __syncthreads();
    }

    #pragma unroll
    for (int im = 0; im < 4; im++) {
        #pragma unroll
        for (int jn = 0; jn < 4; jn++) {
            int mg = mb + wm + 16 * im + g;
            int ng = nb + wn + 8 * jn + 2 * qd;
            float b0v = bp[ng], b1v = bp[ng + 1];
            float2 v01 = make_float2(acc[im][jn][0] + b0v, acc[im][jn][1] + b1v);
            *(float2*)(out + (size_t)mg * CC + ng) = v01;
            float2 v23 = make_float2(acc[im][jn][2] + b0v, acc[im][jn][3] + b1v);
            *(float2*)(out + (size_t)(mg + 8) * CC + ng) = v23;
        }
    }
}

// ---------------------------------------------------------------------------
extern "C" void kernel_launch(void* const* d_in, const int* in_sizes, int n_in,
                              void* d_out, int out_size)
{
    const float* x  = (const float*)d_in[0];
    const float* Wq = (const float*)d_in[1];
    const float* Wk = (const float*)d_in[2];
    const float* Wv = (const float*)d_in[3];
    const float* Wp = (const float*)d_in[4];
    const float* bp = (const float*)d_in[5];
    float* out = (float*)d_out;

    static bool attr_set = false;
    const int gemm_smem = 4 * STGW * 4;     // 73728 B
    if (!attr_set) {
        cudaFuncSetAttribute(qkv_gemm_kernel,  cudaFuncAttributeMaxDynamicSharedMemorySize, gemm_smem);
        cudaFuncSetAttribute(proj_gemm_kernel, cudaFuncAttributeMaxDynamicSharedMemorySize, gemm_smem);
        cudaFuncSetAttribute(attn_kernel,      cudaFuncAttributeMaxDynamicSharedMemorySize, ATTN_SMEM);
        attr_set = true;
    }

    conv_x_kernel<<<MTOT * CC / (256 * 4), 256>>>(x);
    pack_w_kernel<<<(NQKV * CC + 255) / 256, 256>>>(Wq, Wk, Wv, Wp);
    qkv_gemm_kernel<<<dim3(9, 256), 256, gemm_smem>>>();
    attn_kernel<<<dim3(BB * HH, 2), 256, ATTN_SMEM>>>();
    proj_gemm_kernel<<<dim3(3, 256), 256, gemm_smem>>>(bp, out);
}